// round 6
// baseline (speedup 1.0000x reference)
#include <cuda_runtime.h>
#include <cuda_bf16.h>
#include <math.h>
#include <stdint.h>

#define SEQ   2048
#define BATCH 128
#define FEAT  256
#define NPOS  1024
#define NM1   1023
#define BF    (BATCH * FEAT)       // row stride in elements (32768)

// ---------------- scratch (device globals; no allocation allowed) ------------
__device__ int d_cnt0[BF];         // rows 0-127 from tile(0,0), rows 128-255 from tile(1,1)
__device__ int d_cnt1[BF];         // rows 0-127 from tile(0,1)
__device__ int d_order[BF];
__device__ int d_counts[BATCH];

// ---------------- Phase 1+2 fused: triangular tf32 SYRK + stats + counts -----
// grid (3, BATCH): p -> (ti,tj) = (0,0),(0,1),(1,1); 128x128 output tile.
// 512 threads = 16 warps (4x4), warp tile 32x32, thread: 2x4 frags of 4 accums.
// Mainloop: raw G = X^T X (tf32 mma) + per-feature sum/sumsq on the fly.
// Epilogue: cov*(n-1) = r_i r_j (G - n m_i m_j); smem row counts; one store.
#define BK     16
#define NCHUNK (NPOS / BK)

__device__ __forceinline__ uint32_t f2tf32(float v) {
    uint32_t r; asm("cvt.rna.tf32.f32 %0, %1;" : "=r"(r) : "f"(v)); return r;
}
// 128-wide tile swizzle: conflict-free float4 stores + mma frag loads.
__device__ __forceinline__ int swz(int k, int f) {
    return k * 128 + (f ^ ((k & 3) << 3));
}

__global__ void __launch_bounds__(512, 1) cov_kernel(const float* __restrict__ x) {
    __shared__ uint32_t sA[2][BK * 128];       // 16 KB
    __shared__ uint32_t sB[2][BK * 128];       // 16 KB
    __shared__ float smean_i[128], srstd_i[128];
    __shared__ float smean_j[128], srstd_j[128];
    __shared__ int   scnt[128];

    int b   = blockIdx.y;
    int p   = blockIdx.x;                      // 0,1,2
    int ti  = p >> 1, tj = (p + 1) >> 1;
    bool diag = (ti == tj);
    int i0  = ti * 128, j0 = tj * 128;

    int tid  = threadIdx.x;
    int lane = tid & 31;
    int w    = tid >> 5;                       // 0..15
    int wm   = w & 3, wn = w >> 2;             // 4x4 warp grid
    int gid  = lane >> 2, tig = lane & 3;      // mma thread mapping

    const float* xb = x + (size_t)b * FEAT;

    // loader: thread owns (k=w, float4 f4) slot; 1 float4 per tile per chunk
    int f4    = tid & 31;
    int kk    = tid >> 5;                      // == w, 0..15
    int fbase = f4 * 4;

    float acc[2][4][4];
#pragma unroll
    for (int m = 0; m < 2; m++)
#pragma unroll
        for (int n = 0; n < 4; n++)
#pragma unroll
            for (int c = 0; c < 4; c++) acc[m][n][c] = 0.f;

    float sumA[4] = {0,0,0,0}, sqA[4] = {0,0,0,0};
    float sumB[4] = {0,0,0,0}, sqB[4] = {0,0,0,0};

    // prefetch + store chunk 0 (stats accumulated at store time, once per chunk)
    float4 rA = *(const float4*)(xb + (size_t)kk * BF + i0 + fbase);
    float4 rB;
    if (!diag) rB = *(const float4*)(xb + (size_t)kk * BF + j0 + fbase);
    {
        sumA[0]+=rA.x; sqA[0]+=rA.x*rA.x; sumA[1]+=rA.y; sqA[1]+=rA.y*rA.y;
        sumA[2]+=rA.z; sqA[2]+=rA.z*rA.z; sumA[3]+=rA.w; sqA[3]+=rA.w*rA.w;
        *(uint4*)&sA[0][swz(kk, fbase)] =
            make_uint4(f2tf32(rA.x), f2tf32(rA.y), f2tf32(rA.z), f2tf32(rA.w));
        if (!diag) {
            sumB[0]+=rB.x; sqB[0]+=rB.x*rB.x; sumB[1]+=rB.y; sqB[1]+=rB.y*rB.y;
            sumB[2]+=rB.z; sqB[2]+=rB.z*rB.z; sumB[3]+=rB.w; sqB[3]+=rB.w*rB.w;
            *(uint4*)&sB[0][swz(kk, fbase)] =
                make_uint4(f2tf32(rB.x), f2tf32(rB.y), f2tf32(rB.z), f2tf32(rB.w));
        }
    }
    __syncthreads();

    int fmBase = wm * 32 + gid;                // + mt*16 (+8)
    int fnBase = wn * 32 + gid;                // + nt*8

    for (int c = 0; c < NCHUNK; c++) {
        int buf = c & 1;
        if (c + 1 < NCHUNK) {
            size_t off = (size_t)((c + 1) * BK + kk) * BF;
            rA = *(const float4*)(xb + off + i0 + fbase);
            if (!diag) rB = *(const float4*)(xb + off + j0 + fbase);
        }
        const uint32_t* a  = sA[buf];
        const uint32_t* bb = diag ? sA[buf] : sB[buf];

#pragma unroll
        for (int ks = 0; ks < 2; ks++) {
            int k0 = ks * 8 + tig;
            uint32_t af[2][4];
#pragma unroll
            for (int mt = 0; mt < 2; mt++) {
                int fm = fmBase + mt * 16;
                af[mt][0] = a[swz(k0,     fm)];
                af[mt][1] = a[swz(k0,     fm + 8)];
                af[mt][2] = a[swz(k0 + 4, fm)];
                af[mt][3] = a[swz(k0 + 4, fm + 8)];
            }
#pragma unroll
            for (int nt = 0; nt < 4; nt++) {
                int fn = fnBase + nt * 8;
                uint32_t b0 = bb[swz(k0,     fn)];
                uint32_t b1 = bb[swz(k0 + 4, fn)];
#pragma unroll
                for (int mt = 0; mt < 2; mt++) {
                    asm volatile(
                        "mma.sync.aligned.m16n8k8.row.col.f32.tf32.tf32.f32 "
                        "{%0,%1,%2,%3},{%4,%5,%6,%7},{%8,%9},{%0,%1,%2,%3};"
                        : "+f"(acc[mt][nt][0]), "+f"(acc[mt][nt][1]),
                          "+f"(acc[mt][nt][2]), "+f"(acc[mt][nt][3])
                        : "r"(af[mt][0]), "r"(af[mt][1]), "r"(af[mt][2]), "r"(af[mt][3]),
                          "r"(b0), "r"(b1));
                }
            }
        }

        if (c + 1 < NCHUNK) {
            int nb = (c + 1) & 1;
            sumA[0]+=rA.x; sqA[0]+=rA.x*rA.x; sumA[1]+=rA.y; sqA[1]+=rA.y*rA.y;
            sumA[2]+=rA.z; sqA[2]+=rA.z*rA.z; sumA[3]+=rA.w; sqA[3]+=rA.w*rA.w;
            *(uint4*)&sA[nb][swz(kk, fbase)] =
                make_uint4(f2tf32(rA.x), f2tf32(rA.y), f2tf32(rA.z), f2tf32(rA.w));
            if (!diag) {
                sumB[0]+=rB.x; sqB[0]+=rB.x*rB.x; sumB[1]+=rB.y; sqB[1]+=rB.y*rB.y;
                sumB[2]+=rB.z; sqB[2]+=rB.z*rB.z; sumB[3]+=rB.w; sqB[3]+=rB.w*rB.w;
                *(uint4*)&sB[nb][swz(kk, fbase)] =
                    make_uint4(f2tf32(rB.x), f2tf32(rB.y), f2tf32(rB.z), f2tf32(rB.w));
            }
        }
        __syncthreads();
    }

    // ---- stats reduction (reuse tile buffers as plain float scratch) ----
    {
        float* pSumA = (float*)sA[0];  float* pSqA = (float*)sA[1];
        float* pSumB = (float*)sB[0];  float* pSqB = (float*)sB[1];
        *(float4*)&pSumA[kk * 128 + fbase] = make_float4(sumA[0], sumA[1], sumA[2], sumA[3]);
        *(float4*)&pSqA [kk * 128 + fbase] = make_float4(sqA[0],  sqA[1],  sqA[2],  sqA[3]);
        if (!diag) {
            *(float4*)&pSumB[kk * 128 + fbase] = make_float4(sumB[0], sumB[1], sumB[2], sumB[3]);
            *(float4*)&pSqB [kk * 128 + fbase] = make_float4(sqB[0],  sqB[1],  sqB[2],  sqB[3]);
        }
        __syncthreads();

        if (tid < 128) {
            float s = 0.f, q = 0.f;
#pragma unroll
            for (int k = 0; k < BK; k++) { s += pSumA[k * 128 + tid]; q += pSqA[k * 128 + tid]; }
            float mean = s * (1.0f / NPOS);
            float var  = fmaxf((q - s * mean) * (1.0f / NM1), 0.0f);
            smean_i[tid] = mean;
            srstd_i[tid] = 1.0f / (sqrtf(var) + 1e-6f);
        } else if (tid < 256) {
            int f = tid - 128;
            const float* ps = diag ? (float*)sA[0] : (float*)sB[0];
            const float* pq = diag ? (float*)sA[1] : (float*)sB[1];
            float s = 0.f, q = 0.f;
#pragma unroll
            for (int k = 0; k < BK; k++) { s += ps[k * 128 + f]; q += pq[k * 128 + f]; }
            float mean = s * (1.0f / NPOS);
            float var  = fmaxf((q - s * mean) * (1.0f / NM1), 0.0f);
            smean_j[f] = mean;
            srstd_j[f] = 1.0f / (sqrtf(var) + 1e-6f);
        } else if (tid < 384) {
            scnt[tid - 256] = 0;
        }
        __syncthreads();
    }

    // ---- epilogue: threshold + per-row counts (smem, deterministic) ----
    const float thr = 0.999f * (float)NM1;
#pragma unroll
    for (int mt = 0; mt < 2; mt++) {
#pragma unroll
        for (int rr = 0; rr < 2; rr++) {
            int gi = fmBase + mt * 16 + rr * 8;      // 0..127 local row
            float mi = smean_i[gi], ri = srstd_i[gi];
#pragma unroll
            for (int nt = 0; nt < 4; nt++) {
#pragma unroll
                for (int cc = 0; cc < 2; cc++) {
                    int gj = fnBase - gid + nt * 8 + tig * 2 + cc;   // 0..127 local col
                    if (!diag || gi <= gj) {
                        float v = (acc[mt][nt][rr * 2 + cc]
                                   - 1024.0f * mi * smean_j[gj]) * ri * srstd_j[gj];
                        if (v > thr) atomicAdd(&scnt[gi], 1);        // rare except diag
                    }
                }
            }
        }
    }
    __syncthreads();

    if (tid < 128) {
        int rowbase = (p == 2) ? 128 : 0;
        int* dst = (p == 1) ? d_cnt1 : d_cnt0;
        dst[b * FEAT + rowbase + tid] = scnt[tid];
    }
}

// ---------------- Phase 3: stable partition via ballot prefix ----------------
__global__ void select_kernel() {
    int b = blockIdx.x;
    int f = threadIdx.x;
    int w = f >> 5, lane = f & 31;

    int cnt = d_cnt0[b * FEAT + f] + (f < 128 ? d_cnt1[b * FEAT + f] : 0);
    bool sel = (cnt == 1);

    unsigned m = __ballot_sync(0xffffffffu, sel);
    int before = __popc(m & ((1u << lane) - 1));

    __shared__ int wtot[8];
    if (lane == 0) wtot[w] = __popc(m);
    __syncthreads();

    int wpre = 0, tot = 0;
#pragma unroll
    for (int i = 0; i < 8; i++) { if (i < w) wpre += wtot[i]; tot += wtot[i]; }

    int selBefore = wpre + before;
    int pos = sel ? selBefore : tot + (f - selBefore);
    d_order[b * FEAT + pos] = f;
    if (f == 0) d_counts[b] = tot;
}

// ---------------- Phase 4: gather + mask over full SEQ ----------------------
#define ROWS_PER_BLOCK 8
__global__ void gather_kernel(const float* __restrict__ x, float* __restrict__ out) {
    int blk = blockIdx.x;
    int b   = blk % BATCH;
    int s0  = (blk / BATCH) * ROWS_PER_BLOCK;
    int tid = threadIdx.x;

    if (d_counts[b] == FEAT) {   // identity order + all-ones mask -> float4 copy
        const float4* src = (const float4*)(x   + (size_t)s0 * BF + (size_t)b * FEAT);
        float4*       dst = (float4*)      (out + (size_t)s0 * BF + (size_t)b * FEAT);
#pragma unroll
        for (int i = 0; i < 2; i++) {
            int idx = tid + i * 256;
            int r = idx >> 6, f = idx & 63;
            dst[(size_t)r * (BF / 4) + f] = src[(size_t)r * (BF / 4) + f];
        }
        return;
    }

    int  src  = d_order[b * FEAT + tid];
    bool keep = tid < d_counts[b];
    size_t base = (size_t)b * FEAT;
#pragma unroll
    for (int r = 0; r < ROWS_PER_BLOCK; r++) {
        size_t off = (size_t)(s0 + r) * BF + base;
        out[off + tid] = keep ? x[off + src] : 0.0f;
    }
}

// ---------------- launch -----------------------------------------------------
extern "C" void kernel_launch(void* const* d_in, const int* in_sizes, int n_in,
                              void* d_out, int out_size) {
    const float* x = (const float*)d_in[0];
    float* out = (float*)d_out;
    (void)in_sizes; (void)n_in; (void)out_size;

    cov_kernel   <<<dim3(3, BATCH), 512>>>(x);
    select_kernel<<<BATCH, FEAT>>>();
    gather_kernel<<<(SEQ / ROWS_PER_BLOCK) * BATCH, FEAT>>>(x, out);
}

// round 7
// speedup vs baseline: 1.0858x; 1.0858x over previous
#include <cuda_runtime.h>
#include <cuda_bf16.h>
#include <math.h>
#include <stdint.h>

#define SEQ   2048
#define BATCH 128
#define FEAT  256
#define NPOS  1024
#define NM1   1023
#define BF    (BATCH * FEAT)       // row stride in elements (32768)

// ---------------- scratch (device globals; no allocation allowed) ------------
__device__ int d_cnt0[BF];         // rows 0-127 from tile(0,0), rows 128-255 from tile(1,1)
__device__ int d_cnt1[BF];         // rows 0-127 from tile(0,1)
__device__ int d_order[BF];
__device__ int d_counts[BATCH];

// ---------------- Phase 1+2 fused: triangular tf32 SYRK + stats + counts -----
// grid (3, BATCH): p -> (ti,tj) = (0,0),(0,1),(1,1); 128x128 output tile.
// 256 threads = 8 warps in 4x2 grid; warp tile 32x64; thread: 2x8 frags x4 acc.
// 32 mma per warp per sync interval; 2 CTAs/SM for cross-CTA barrier overlap.
#define BK     16
#define NCHUNK (NPOS / BK)

__device__ __forceinline__ uint32_t f2tf32(float v) {
    uint32_t r; asm("cvt.rna.tf32.f32 %0, %1;" : "=r"(r) : "f"(v)); return r;
}
// 128-wide tile swizzle: conflict-free float4 stores + mma frag loads.
__device__ __forceinline__ int swz(int k, int f) {
    return k * 128 + (f ^ ((k & 3) << 3));
}

__global__ void __launch_bounds__(256, 2) cov_kernel(const float* __restrict__ x) {
    __shared__ uint32_t sA[2][BK * 128];       // 2 x 8 KB
    __shared__ uint32_t sB[2][BK * 128];       // 2 x 8 KB
    __shared__ float smean_i[128], srstd_i[128];
    __shared__ float smean_j[128], srstd_j[128];
    __shared__ int   scnt[128];

    int b   = blockIdx.y;
    int p   = blockIdx.x;                      // 0,1,2
    int ti  = p >> 1, tj = (p + 1) >> 1;
    bool diag = (ti == tj);
    int i0  = ti * 128, j0 = tj * 128;

    int tid  = threadIdx.x;
    int lane = tid & 31;
    int w    = tid >> 5;                       // 0..7
    int wm   = w & 3, wn = w >> 2;             // 4x2 warp grid
    int gid  = lane >> 2, tig = lane & 3;      // mma thread mapping

    const float* xb = x + (size_t)b * FEAT;

    // loader: thread owns k rows {kk, kk+8} x one float4 column slot
    int kk    = tid >> 5;                      // 0..7
    int fbase = (tid & 31) * 4;

    float acc[2][8][4];
#pragma unroll
    for (int m = 0; m < 2; m++)
#pragma unroll
        for (int n = 0; n < 8; n++)
#pragma unroll
            for (int c = 0; c < 4; c++) acc[m][n][c] = 0.f;

    float sumA[4] = {0,0,0,0}, sqA[4] = {0,0,0,0};
    float sumB[4] = {0,0,0,0}, sqB[4] = {0,0,0,0};

    // prefetch + store chunk 0 (stats accumulated once per chunk at store time)
    float4 rA0 = *(const float4*)(xb + (size_t)kk * BF + i0 + fbase);
    float4 rA1 = *(const float4*)(xb + (size_t)(kk + 8) * BF + i0 + fbase);
    float4 rB0, rB1;
    if (!diag) {
        rB0 = *(const float4*)(xb + (size_t)kk * BF + j0 + fbase);
        rB1 = *(const float4*)(xb + (size_t)(kk + 8) * BF + j0 + fbase);
    }
    {
        sumA[0]+=rA0.x+rA1.x; sqA[0]+=rA0.x*rA0.x+rA1.x*rA1.x;
        sumA[1]+=rA0.y+rA1.y; sqA[1]+=rA0.y*rA0.y+rA1.y*rA1.y;
        sumA[2]+=rA0.z+rA1.z; sqA[2]+=rA0.z*rA0.z+rA1.z*rA1.z;
        sumA[3]+=rA0.w+rA1.w; sqA[3]+=rA0.w*rA0.w+rA1.w*rA1.w;
        *(uint4*)&sA[0][swz(kk, fbase)] =
            make_uint4(f2tf32(rA0.x), f2tf32(rA0.y), f2tf32(rA0.z), f2tf32(rA0.w));
        *(uint4*)&sA[0][swz(kk + 8, fbase)] =
            make_uint4(f2tf32(rA1.x), f2tf32(rA1.y), f2tf32(rA1.z), f2tf32(rA1.w));
        if (!diag) {
            sumB[0]+=rB0.x+rB1.x; sqB[0]+=rB0.x*rB0.x+rB1.x*rB1.x;
            sumB[1]+=rB0.y+rB1.y; sqB[1]+=rB0.y*rB0.y+rB1.y*rB1.y;
            sumB[2]+=rB0.z+rB1.z; sqB[2]+=rB0.z*rB0.z+rB1.z*rB1.z;
            sumB[3]+=rB0.w+rB1.w; sqB[3]+=rB0.w*rB0.w+rB1.w*rB1.w;
            *(uint4*)&sB[0][swz(kk, fbase)] =
                make_uint4(f2tf32(rB0.x), f2tf32(rB0.y), f2tf32(rB0.z), f2tf32(rB0.w));
            *(uint4*)&sB[0][swz(kk + 8, fbase)] =
                make_uint4(f2tf32(rB1.x), f2tf32(rB1.y), f2tf32(rB1.z), f2tf32(rB1.w));
        }
    }
    __syncthreads();

    int fmBase = wm * 32 + gid;                // + mt*16 (+8)
    int fnBase = wn * 64 + gid;                // + nt*8

    for (int c = 0; c < NCHUNK; c++) {
        int buf = c & 1;
        if (c + 1 < NCHUNK) {
            size_t off = (size_t)((c + 1) * BK) * BF;
            rA0 = *(const float4*)(xb + off + (size_t)kk * BF + i0 + fbase);
            rA1 = *(const float4*)(xb + off + (size_t)(kk + 8) * BF + i0 + fbase);
            if (!diag) {
                rB0 = *(const float4*)(xb + off + (size_t)kk * BF + j0 + fbase);
                rB1 = *(const float4*)(xb + off + (size_t)(kk + 8) * BF + j0 + fbase);
            }
        }
        const uint32_t* a  = sA[buf];
        const uint32_t* bb = diag ? sA[buf] : sB[buf];

#pragma unroll
        for (int ks = 0; ks < 2; ks++) {
            int k0 = ks * 8 + tig;
            uint32_t af[2][4];
#pragma unroll
            for (int mt = 0; mt < 2; mt++) {
                int fm = fmBase + mt * 16;
                af[mt][0] = a[swz(k0,     fm)];
                af[mt][1] = a[swz(k0,     fm + 8)];
                af[mt][2] = a[swz(k0 + 4, fm)];
                af[mt][3] = a[swz(k0 + 4, fm + 8)];
            }
#pragma unroll
            for (int nt = 0; nt < 8; nt++) {
                int fn = fnBase + nt * 8;
                uint32_t b0 = bb[swz(k0,     fn)];
                uint32_t b1 = bb[swz(k0 + 4, fn)];
#pragma unroll
                for (int mt = 0; mt < 2; mt++) {
                    asm volatile(
                        "mma.sync.aligned.m16n8k8.row.col.f32.tf32.tf32.f32 "
                        "{%0,%1,%2,%3},{%4,%5,%6,%7},{%8,%9},{%0,%1,%2,%3};"
                        : "+f"(acc[mt][nt][0]), "+f"(acc[mt][nt][1]),
                          "+f"(acc[mt][nt][2]), "+f"(acc[mt][nt][3])
                        : "r"(af[mt][0]), "r"(af[mt][1]), "r"(af[mt][2]), "r"(af[mt][3]),
                          "r"(b0), "r"(b1));
                }
            }
        }

        if (c + 1 < NCHUNK) {
            int nb = (c + 1) & 1;
            sumA[0]+=rA0.x+rA1.x; sqA[0]+=rA0.x*rA0.x+rA1.x*rA1.x;
            sumA[1]+=rA0.y+rA1.y; sqA[1]+=rA0.y*rA0.y+rA1.y*rA1.y;
            sumA[2]+=rA0.z+rA1.z; sqA[2]+=rA0.z*rA0.z+rA1.z*rA1.z;
            sumA[3]+=rA0.w+rA1.w; sqA[3]+=rA0.w*rA0.w+rA1.w*rA1.w;
            *(uint4*)&sA[nb][swz(kk, fbase)] =
                make_uint4(f2tf32(rA0.x), f2tf32(rA0.y), f2tf32(rA0.z), f2tf32(rA0.w));
            *(uint4*)&sA[nb][swz(kk + 8, fbase)] =
                make_uint4(f2tf32(rA1.x), f2tf32(rA1.y), f2tf32(rA1.z), f2tf32(rA1.w));
            if (!diag) {
                sumB[0]+=rB0.x+rB1.x; sqB[0]+=rB0.x*rB0.x+rB1.x*rB1.x;
                sumB[1]+=rB0.y+rB1.y; sqB[1]+=rB0.y*rB0.y+rB1.y*rB1.y;
                sumB[2]+=rB0.z+rB1.z; sqB[2]+=rB0.z*rB0.z+rB1.z*rB1.z;
                sumB[3]+=rB0.w+rB1.w; sqB[3]+=rB0.w*rB0.w+rB1.w*rB1.w;
                *(uint4*)&sB[nb][swz(kk, fbase)] =
                    make_uint4(f2tf32(rB0.x), f2tf32(rB0.y), f2tf32(rB0.z), f2tf32(rB0.w));
                *(uint4*)&sB[nb][swz(kk + 8, fbase)] =
                    make_uint4(f2tf32(rB1.x), f2tf32(rB1.y), f2tf32(rB1.z), f2tf32(rB1.w));
            }
        }
        __syncthreads();
    }

    // ---- stats reduction (reuse tile buffers as plain float scratch) ----
    {
        float* pSumA = (float*)sA[0];  float* pSqA = (float*)sA[1];
        float* pSumB = (float*)sB[0];  float* pSqB = (float*)sB[1];
        *(float4*)&pSumA[kk * 128 + fbase] = make_float4(sumA[0], sumA[1], sumA[2], sumA[3]);
        *(float4*)&pSqA [kk * 128 + fbase] = make_float4(sqA[0],  sqA[1],  sqA[2],  sqA[3]);
        if (!diag) {
            *(float4*)&pSumB[kk * 128 + fbase] = make_float4(sumB[0], sumB[1], sumB[2], sumB[3]);
            *(float4*)&pSqB [kk * 128 + fbase] = make_float4(sqB[0],  sqB[1],  sqB[2],  sqB[3]);
        }
        __syncthreads();

        if (tid < 128) {
            float s = 0.f, q = 0.f;
#pragma unroll
            for (int k = 0; k < 8; k++) { s += pSumA[k * 128 + tid]; q += pSqA[k * 128 + tid]; }
            float mean = s * (1.0f / NPOS);
            float var  = fmaxf((q - s * mean) * (1.0f / NM1), 0.0f);
            smean_i[tid] = mean;
            srstd_i[tid] = 1.0f / (sqrtf(var) + 1e-6f);
            scnt[tid] = 0;
        } else {
            int f = tid - 128;
            const float* ps = diag ? (float*)sA[0] : (float*)sB[0];
            const float* pq = diag ? (float*)sA[1] : (float*)sB[1];
            float s = 0.f, q = 0.f;
#pragma unroll
            for (int k = 0; k < 8; k++) { s += ps[k * 128 + f]; q += pq[k * 128 + f]; }
            float mean = s * (1.0f / NPOS);
            float var  = fmaxf((q - s * mean) * (1.0f / NM1), 0.0f);
            smean_j[f] = mean;
            srstd_j[f] = 1.0f / (sqrtf(var) + 1e-6f);
        }
        __syncthreads();
    }

    // ---- epilogue: threshold + per-row counts (smem, deterministic) ----
    const float thr = 0.999f * (float)NM1;
#pragma unroll
    for (int mt = 0; mt < 2; mt++) {
#pragma unroll
        for (int rr = 0; rr < 2; rr++) {
            int gi = fmBase + mt * 16 + rr * 8;      // 0..127 local row
            float mi = smean_i[gi], ri = srstd_i[gi];
#pragma unroll
            for (int nt = 0; nt < 8; nt++) {
#pragma unroll
                for (int cc = 0; cc < 2; cc++) {
                    int gj = wn * 64 + nt * 8 + tig * 2 + cc;   // 0..127 local col
                    if (!diag || gi <= gj) {
                        float v = (acc[mt][nt][rr * 2 + cc]
                                   - 1024.0f * mi * smean_j[gj]) * ri * srstd_j[gj];
                        if (v > thr) atomicAdd(&scnt[gi], 1);   // rare except diag
                    }
                }
            }
        }
    }
    __syncthreads();

    if (tid < 128) {
        int rowbase = (p == 2) ? 128 : 0;
        int* dst = (p == 1) ? d_cnt1 : d_cnt0;
        dst[b * FEAT + rowbase + tid] = scnt[tid];
    }
}

// ---------------- Phase 3: stable partition via ballot prefix ----------------
__global__ void select_kernel() {
    int b = blockIdx.x;
    int f = threadIdx.x;
    int w = f >> 5, lane = f & 31;

    int cnt = d_cnt0[b * FEAT + f] + (f < 128 ? d_cnt1[b * FEAT + f] : 0);
    bool sel = (cnt == 1);

    unsigned m = __ballot_sync(0xffffffffu, sel);
    int before = __popc(m & ((1u << lane) - 1));

    __shared__ int wtot[8];
    if (lane == 0) wtot[w] = __popc(m);
    __syncthreads();

    int wpre = 0, tot = 0;
#pragma unroll
    for (int i = 0; i < 8; i++) { if (i < w) wpre += wtot[i]; tot += wtot[i]; }

    int selBefore = wpre + before;
    int pos = sel ? selBefore : tot + (f - selBefore);
    d_order[b * FEAT + pos] = f;
    if (f == 0) d_counts[b] = tot;
}

// ---------------- Phase 4: gather + mask over full SEQ ----------------------
#define ROWS_PER_BLOCK 8
__global__ void gather_kernel(const float* __restrict__ x, float* __restrict__ out) {
    int blk = blockIdx.x;
    int b   = blk % BATCH;
    int s0  = (blk / BATCH) * ROWS_PER_BLOCK;
    int tid = threadIdx.x;

    if (d_counts[b] == FEAT) {   // identity order + all-ones mask -> float4 copy
        const float4* src = (const float4*)(x   + (size_t)s0 * BF + (size_t)b * FEAT);
        float4*       dst = (float4*)      (out + (size_t)s0 * BF + (size_t)b * FEAT);
#pragma unroll
        for (int i = 0; i < 2; i++) {
            int idx = tid + i * 256;
            int r = idx >> 6, f = idx & 63;
            dst[(size_t)r * (BF / 4) + f] = src[(size_t)r * (BF / 4) + f];
        }
        return;
    }

    int  src  = d_order[b * FEAT + tid];
    bool keep = tid < d_counts[b];
    size_t base = (size_t)b * FEAT;
#pragma unroll
    for (int r = 0; r < ROWS_PER_BLOCK; r++) {
        size_t off = (size_t)(s0 + r) * BF + base;
        out[off + tid] = keep ? x[off + src] : 0.0f;
    }
}

// ---------------- launch -----------------------------------------------------
extern "C" void kernel_launch(void* const* d_in, const int* in_sizes, int n_in,
                              void* d_out, int out_size) {
    const float* x = (const float*)d_in[0];
    float* out = (float*)d_out;
    (void)in_sizes; (void)n_in; (void)out_size;

    cov_kernel   <<<dim3(3, BATCH), 256>>>(x);
    select_kernel<<<BATCH, FEAT>>>();
    gather_kernel<<<(SEQ / ROWS_PER_BLOCK) * BATCH, FEAT>>>(x, out);
}

// round 8
// speedup vs baseline: 1.0865x; 1.0006x over previous
#include <cuda_runtime.h>
#include <cuda_bf16.h>
#include <math.h>
#include <stdint.h>

#define SEQ   2048
#define BATCH 128
#define FEAT  256
#define NPOS  1024
#define NM1   1023
#define BF    (BATCH * FEAT)       // row stride in elements (32768)

// ---------------- scratch (device globals; no allocation allowed) ------------
__device__ int d_cnt0[BF];         // rows 0-127 from tile(0,0), rows 128-255 from tile(1,1)
__device__ int d_cnt1[BF];         // rows 0-127 from tile(0,1)
__device__ int d_order[BF];
__device__ int d_counts[BATCH];

// ---------------- Phase 1+2 fused: triangular tf32 SYRK + stats + counts -----
// grid (3, BATCH): p -> (ti,tj) = (0,0),(0,1),(1,1); 128x128 output tile.
// 256 threads = 8 warps in 4x2 grid; warp tile 32x64; thread: 2x8 frags x4 acc.
// 32 mma per warp per sync interval; 2 CTAs/SM for cross-CTA barrier overlap.
#define BK     16
#define NCHUNK (NPOS / BK)

__device__ __forceinline__ uint32_t f2tf32(float v) {
    uint32_t r; asm("cvt.rna.tf32.f32 %0, %1;" : "=r"(r) : "f"(v)); return r;
}
// 128-wide tile swizzle: conflict-free float4 stores + mma frag loads.
__device__ __forceinline__ int swz(int k, int f) {
    return k * 128 + (f ^ ((k & 3) << 3));
}

__global__ void __launch_bounds__(256, 2) cov_kernel(const float* __restrict__ x) {
    __shared__ uint32_t sA[2][BK * 128];       // 2 x 8 KB
    __shared__ uint32_t sB[2][BK * 128];       // 2 x 8 KB
    __shared__ float smean_i[128], srstd_i[128];
    __shared__ float smean_j[128], srstd_j[128];
    __shared__ int   scnt[128];

    int b   = blockIdx.y;
    int p   = blockIdx.x;                      // 0,1,2
    int ti  = p >> 1, tj = (p + 1) >> 1;
    bool diag = (ti == tj);
    int i0  = ti * 128, j0 = tj * 128;

    int tid  = threadIdx.x;
    int lane = tid & 31;
    int w    = tid >> 5;                       // 0..7
    int wm   = w & 3, wn = w >> 2;             // 4x2 warp grid
    int gid  = lane >> 2, tig = lane & 3;      // mma thread mapping

    const float* xb = x + (size_t)b * FEAT;

    // loader: thread owns k rows {kk, kk+8} x one float4 column slot
    int kk    = tid >> 5;                      // 0..7
    int fbase = (tid & 31) * 4;

    float acc[2][8][4];
#pragma unroll
    for (int m = 0; m < 2; m++)
#pragma unroll
        for (int n = 0; n < 8; n++)
#pragma unroll
            for (int c = 0; c < 4; c++) acc[m][n][c] = 0.f;

    float sumA[4] = {0,0,0,0}, sqA[4] = {0,0,0,0};
    float sumB[4] = {0,0,0,0}, sqB[4] = {0,0,0,0};

    // prefetch + store chunk 0 (stats accumulated once per chunk at store time)
    float4 rA0 = *(const float4*)(xb + (size_t)kk * BF + i0 + fbase);
    float4 rA1 = *(const float4*)(xb + (size_t)(kk + 8) * BF + i0 + fbase);
    float4 rB0, rB1;
    if (!diag) {
        rB0 = *(const float4*)(xb + (size_t)kk * BF + j0 + fbase);
        rB1 = *(const float4*)(xb + (size_t)(kk + 8) * BF + j0 + fbase);
    }
    {
        sumA[0]+=rA0.x+rA1.x; sqA[0]+=rA0.x*rA0.x+rA1.x*rA1.x;
        sumA[1]+=rA0.y+rA1.y; sqA[1]+=rA0.y*rA0.y+rA1.y*rA1.y;
        sumA[2]+=rA0.z+rA1.z; sqA[2]+=rA0.z*rA0.z+rA1.z*rA1.z;
        sumA[3]+=rA0.w+rA1.w; sqA[3]+=rA0.w*rA0.w+rA1.w*rA1.w;
        *(uint4*)&sA[0][swz(kk, fbase)] =
            make_uint4(f2tf32(rA0.x), f2tf32(rA0.y), f2tf32(rA0.z), f2tf32(rA0.w));
        *(uint4*)&sA[0][swz(kk + 8, fbase)] =
            make_uint4(f2tf32(rA1.x), f2tf32(rA1.y), f2tf32(rA1.z), f2tf32(rA1.w));
        if (!diag) {
            sumB[0]+=rB0.x+rB1.x; sqB[0]+=rB0.x*rB0.x+rB1.x*rB1.x;
            sumB[1]+=rB0.y+rB1.y; sqB[1]+=rB0.y*rB0.y+rB1.y*rB1.y;
            sumB[2]+=rB0.z+rB1.z; sqB[2]+=rB0.z*rB0.z+rB1.z*rB1.z;
            sumB[3]+=rB0.w+rB1.w; sqB[3]+=rB0.w*rB0.w+rB1.w*rB1.w;
            *(uint4*)&sB[0][swz(kk, fbase)] =
                make_uint4(f2tf32(rB0.x), f2tf32(rB0.y), f2tf32(rB0.z), f2tf32(rB0.w));
            *(uint4*)&sB[0][swz(kk + 8, fbase)] =
                make_uint4(f2tf32(rB1.x), f2tf32(rB1.y), f2tf32(rB1.z), f2tf32(rB1.w));
        }
    }
    __syncthreads();

    int fmBase = wm * 32 + gid;                // + mt*16 (+8)
    int fnBase = wn * 64 + gid;                // + nt*8

    for (int c = 0; c < NCHUNK; c++) {
        int buf = c & 1;
        if (c + 1 < NCHUNK) {
            size_t off = (size_t)((c + 1) * BK) * BF;
            rA0 = *(const float4*)(xb + off + (size_t)kk * BF + i0 + fbase);
            rA1 = *(const float4*)(xb + off + (size_t)(kk + 8) * BF + i0 + fbase);
            if (!diag) {
                rB0 = *(const float4*)(xb + off + (size_t)kk * BF + j0 + fbase);
                rB1 = *(const float4*)(xb + off + (size_t)(kk + 8) * BF + j0 + fbase);
            }
        }
        const uint32_t* a  = sA[buf];
        const uint32_t* bb = diag ? sA[buf] : sB[buf];

#pragma unroll
        for (int ks = 0; ks < 2; ks++) {
            int k0 = ks * 8 + tig;
            uint32_t af[2][4];
#pragma unroll
            for (int mt = 0; mt < 2; mt++) {
                int fm = fmBase + mt * 16;
                af[mt][0] = a[swz(k0,     fm)];
                af[mt][1] = a[swz(k0,     fm + 8)];
                af[mt][2] = a[swz(k0 + 4, fm)];
                af[mt][3] = a[swz(k0 + 4, fm + 8)];
            }
#pragma unroll
            for (int nt = 0; nt < 8; nt++) {
                int fn = fnBase + nt * 8;
                uint32_t b0 = bb[swz(k0,     fn)];
                uint32_t b1 = bb[swz(k0 + 4, fn)];
#pragma unroll
                for (int mt = 0; mt < 2; mt++) {
                    asm volatile(
                        "mma.sync.aligned.m16n8k8.row.col.f32.tf32.tf32.f32 "
                        "{%0,%1,%2,%3},{%4,%5,%6,%7},{%8,%9},{%0,%1,%2,%3};"
                        : "+f"(acc[mt][nt][0]), "+f"(acc[mt][nt][1]),
                          "+f"(acc[mt][nt][2]), "+f"(acc[mt][nt][3])
                        : "r"(af[mt][0]), "r"(af[mt][1]), "r"(af[mt][2]), "r"(af[mt][3]),
                          "r"(b0), "r"(b1));
                }
            }
        }

        if (c + 1 < NCHUNK) {
            int nb = (c + 1) & 1;
            sumA[0]+=rA0.x+rA1.x; sqA[0]+=rA0.x*rA0.x+rA1.x*rA1.x;
            sumA[1]+=rA0.y+rA1.y; sqA[1]+=rA0.y*rA0.y+rA1.y*rA1.y;
            sumA[2]+=rA0.z+rA1.z; sqA[2]+=rA0.z*rA0.z+rA1.z*rA1.z;
            sumA[3]+=rA0.w+rA1.w; sqA[3]+=rA0.w*rA0.w+rA1.w*rA1.w;
            *(uint4*)&sA[nb][swz(kk, fbase)] =
                make_uint4(f2tf32(rA0.x), f2tf32(rA0.y), f2tf32(rA0.z), f2tf32(rA0.w));
            *(uint4*)&sA[nb][swz(kk + 8, fbase)] =
                make_uint4(f2tf32(rA1.x), f2tf32(rA1.y), f2tf32(rA1.z), f2tf32(rA1.w));
            if (!diag) {
                sumB[0]+=rB0.x+rB1.x; sqB[0]+=rB0.x*rB0.x+rB1.x*rB1.x;
                sumB[1]+=rB0.y+rB1.y; sqB[1]+=rB0.y*rB0.y+rB1.y*rB1.y;
                sumB[2]+=rB0.z+rB1.z; sqB[2]+=rB0.z*rB0.z+rB1.z*rB1.z;
                sumB[3]+=rB0.w+rB1.w; sqB[3]+=rB0.w*rB0.w+rB1.w*rB1.w;
                *(uint4*)&sB[nb][swz(kk, fbase)] =
                    make_uint4(f2tf32(rB0.x), f2tf32(rB0.y), f2tf32(rB0.z), f2tf32(rB0.w));
                *(uint4*)&sB[nb][swz(kk + 8, fbase)] =
                    make_uint4(f2tf32(rB1.x), f2tf32(rB1.y), f2tf32(rB1.z), f2tf32(rB1.w));
            }
        }
        __syncthreads();
    }

    // ---- stats reduction (reuse tile buffers as plain float scratch) ----
    {
        float* pSumA = (float*)sA[0];  float* pSqA = (float*)sA[1];
        float* pSumB = (float*)sB[0];  float* pSqB = (float*)sB[1];
        *(float4*)&pSumA[kk * 128 + fbase] = make_float4(sumA[0], sumA[1], sumA[2], sumA[3]);
        *(float4*)&pSqA [kk * 128 + fbase] = make_float4(sqA[0],  sqA[1],  sqA[2],  sqA[3]);
        if (!diag) {
            *(float4*)&pSumB[kk * 128 + fbase] = make_float4(sumB[0], sumB[1], sumB[2], sumB[3]);
            *(float4*)&pSqB [kk * 128 + fbase] = make_float4(sqB[0],  sqB[1],  sqB[2],  sqB[3]);
        }
        __syncthreads();

        if (tid < 128) {
            float s = 0.f, q = 0.f;
#pragma unroll
            for (int k = 0; k < 8; k++) { s += pSumA[k * 128 + tid]; q += pSqA[k * 128 + tid]; }
            float mean = s * (1.0f / NPOS);
            float var  = fmaxf((q - s * mean) * (1.0f / NM1), 0.0f);
            smean_i[tid] = mean;
            srstd_i[tid] = 1.0f / (sqrtf(var) + 1e-6f);
            scnt[tid] = 0;
        } else {
            int f = tid - 128;
            const float* ps = diag ? (float*)sA[0] : (float*)sB[0];
            const float* pq = diag ? (float*)sA[1] : (float*)sB[1];
            float s = 0.f, q = 0.f;
#pragma unroll
            for (int k = 0; k < 8; k++) { s += ps[k * 128 + f]; q += pq[k * 128 + f]; }
            float mean = s * (1.0f / NPOS);
            float var  = fmaxf((q - s * mean) * (1.0f / NM1), 0.0f);
            smean_j[f] = mean;
            srstd_j[f] = 1.0f / (sqrtf(var) + 1e-6f);
        }
        __syncthreads();
    }

    // ---- epilogue: threshold + per-row counts (smem, deterministic) ----
    const float thr = 0.999f * (float)NM1;
#pragma unroll
    for (int mt = 0; mt < 2; mt++) {
#pragma unroll
        for (int rr = 0; rr < 2; rr++) {
            int gi = fmBase + mt * 16 + rr * 8;      // 0..127 local row
            float mi = smean_i[gi], ri = srstd_i[gi];
#pragma unroll
            for (int nt = 0; nt < 8; nt++) {
#pragma unroll
                for (int cc = 0; cc < 2; cc++) {
                    int gj = wn * 64 + nt * 8 + tig * 2 + cc;   // 0..127 local col
                    if (!diag || gi <= gj) {
                        float v = (acc[mt][nt][rr * 2 + cc]
                                   - 1024.0f * mi * smean_j[gj]) * ri * srstd_j[gj];
                        if (v > thr) atomicAdd(&scnt[gi], 1);   // rare except diag
                    }
                }
            }
        }
    }
    __syncthreads();

    if (tid < 128) {
        int rowbase = (p == 2) ? 128 : 0;
        int* dst = (p == 1) ? d_cnt1 : d_cnt0;
        dst[b * FEAT + rowbase + tid] = scnt[tid];
    }
}

// ---------------- Phase 3: stable partition via ballot prefix ----------------
__global__ void select_kernel() {
    int b = blockIdx.x;
    int f = threadIdx.x;
    int w = f >> 5, lane = f & 31;

    int cnt = d_cnt0[b * FEAT + f] + (f < 128 ? d_cnt1[b * FEAT + f] : 0);
    bool sel = (cnt == 1);

    unsigned m = __ballot_sync(0xffffffffu, sel);
    int before = __popc(m & ((1u << lane) - 1));

    __shared__ int wtot[8];
    if (lane == 0) wtot[w] = __popc(m);
    __syncthreads();

    int wpre = 0, tot = 0;
#pragma unroll
    for (int i = 0; i < 8; i++) { if (i < w) wpre += wtot[i]; tot += wtot[i]; }

    int selBefore = wpre + before;
    int pos = sel ? selBefore : tot + (f - selBefore);
    d_order[b * FEAT + pos] = f;
    if (f == 0) d_counts[b] = tot;
}

// ---------------- Phase 4: gather + mask over full SEQ ----------------------
#define ROWS_PER_BLOCK 8
__global__ void gather_kernel(const float* __restrict__ x, float* __restrict__ out) {
    int blk = blockIdx.x;
    int b   = blk % BATCH;
    int s0  = (blk / BATCH) * ROWS_PER_BLOCK;
    int tid = threadIdx.x;

    if (d_counts[b] == FEAT) {   // identity order + all-ones mask -> float4 copy
        const float4* src = (const float4*)(x   + (size_t)s0 * BF + (size_t)b * FEAT);
        float4*       dst = (float4*)      (out + (size_t)s0 * BF + (size_t)b * FEAT);
#pragma unroll
        for (int i = 0; i < 2; i++) {
            int idx = tid + i * 256;
            int r = idx >> 6, f = idx & 63;
            dst[(size_t)r * (BF / 4) + f] = src[(size_t)r * (BF / 4) + f];
        }
        return;
    }

    int  src  = d_order[b * FEAT + tid];
    bool keep = tid < d_counts[b];
    size_t base = (size_t)b * FEAT;
#pragma unroll
    for (int r = 0; r < ROWS_PER_BLOCK; r++) {
        size_t off = (size_t)(s0 + r) * BF + base;
        out[off + tid] = keep ? x[off + src] : 0.0f;
    }
}

// ---------------- launch -----------------------------------------------------
extern "C" void kernel_launch(void* const* d_in, const int* in_sizes, int n_in,
                              void* d_out, int out_size) {
    const float* x = (const float*)d_in[0];
    float* out = (float*)d_out;
    (void)in_sizes; (void)n_in; (void)out_size;

    cov_kernel   <<<dim3(3, BATCH), 256>>>(x);
    select_kernel<<<BATCH, FEAT>>>();
    gather_kernel<<<(SEQ / ROWS_PER_BLOCK) * BATCH, FEAT>>>(x, out);
}